// round 10
// baseline (speedup 1.0000x reference)
#include <cuda_runtime.h>
#include <cstdint>
#include <cstddef>

// Correlation: out[b, ix*21+iy, h, w] = sum_c f1[b,c,h,w] * f2[b,c,h+2ix-20, w+2iy-20]
// B=4, C=128, H=96, W=192, D=20, stride 2 -> 441 offsets.
//
// Parity FIR: out[u][j] += f1[u] * f2p[u+j-10], smem slot s = u+j in [10,105].
// Small-CTA: 192 thr (2jh x 2q x 2p x 24t), 44 accs, 4 CTAs/SM.
// R10: ALU purge. Staging = 2 float4 slots/thread with real 64-bit pointers
// (1 add + LDG.128 + 2 STS.64 each), uniform parity delta 480B (f1 rows padded
// to 120), split LDG-early/STS-late order (R2), symmetric 11/11 tap split
// (j = 10*jh + jj; j=10 double-stored with bitwise-identical value).
// Layout per c (720 floats): [f1 p0|f1 p1|f2q0 p0|f2q0 p1|f2q1 p0|f2q1 p1]x120.

#define NTHR   192
#define CC     2
#define CROW   720                       // floats per channel block
#define BUFPAD 4096                      // buffer stride (floats) = 16384 B
#define NSEG   (CC * 3 * 48)             // 288 float4 segments per chunk
#define NL     2                         // ceil(288/192)
#define CH_STRIDE 18432                  // 96*192 floats per channel

__global__ void __launch_bounds__(NTHR, 4)
corr_kernel(const float* __restrict__ f1, const float* __restrict__ f2,
            float* __restrict__ out)
{
    extern __shared__ float smem[];

    const int h   = blockIdx.x;   // 0..95
    const int b   = blockIdx.y;   // 0..3
    const int ixg = blockIdx.z;   // 0..10 : ix pair {2*ixg, 2*ixg+1}
    const int tid = threadIdx.x;

    const int jh = tid / 96;           // warp-uniform (96 = 3 warps)
    const int r0 = tid % 96;
    const int q  = r0 / 48;            // ix within pair
    const int r1 = r0 % 48;
    const int p  = r1 / 24;            // parity of w
    const int t  = r1 % 24;            // u-tile
    const int u0 = 4 * t;
    const int ix = 2 * ixg + q;        // 21 = dummy slice (never stored)
    const int h2base = h + 4 * ixg - 20;

    // zero both buffers once: pad slots / OOB rows stay zero forever
    for (int i = tid; i < 2 * BUFPAD; i += NTHR) smem[i] = 0.0f;

    // ---- one-time staging precompute: NL (64-bit gptr, smem byte offset) ----
    const float4* gp[NL];
    int so[NL];                         // byte offset within buffer; -1 invalid
    #pragma unroll
    for (int i = 0; i < NL; i++) {
        so[i] = -1;
        gp[i] = (const float4*)f1;
        int idx = tid + i * NTHR;
        if (idx < NSEG) {
            int c   = idx / 144;
            int rr  = idx - c * 144;
            int row = rr / 48;          // 0=f1, 1..2=f2 (qq=row-1)
            int op  = rr - row * 48;    // 16B segment in source row
            if (row == 0) {
                gp[i] = (const float4*)(f1 + ((size_t)(b*128 + c)*96 + h)*192 + 4*op);
                so[i] = (c * CROW + 2 * op) * 4;            // u=2op (even), +480B odd
            } else {
                int qq = row - 1;
                int h2 = h2base + 2 * qq;
                if ((unsigned)h2 < 96u) {
                    gp[i] = (const float4*)(f2 + ((size_t)(b*128 + c)*96 + h2)*192 + 4*op);
                    so[i] = (c * CROW + (1 + qq) * 240 + (2*op + 10)) * 4;  // s=2op+10
                }
            }
        }
    }

    float acc[44];                     // [k 0..3][jj 0..10]
    #pragma unroll
    for (int i = 0; i < 44; i++) acc[i] = 0.0f;

    float4 v[NL];

    __syncthreads();                   // zeros visible

    // prologue: chunk 0 -> buffer 0
    #pragma unroll
    for (int i = 0; i < NL; i++)
        if (so[i] >= 0) v[i] = *gp[i];
    #pragma unroll
    for (int i = 0; i < NL; i++)
        if (so[i] >= 0) {
            char* d = (char*)smem + so[i];
            *(float2*)(d)       = make_float2(v[i].x, v[i].z);   // even parity
            *(float2*)(d + 480) = make_float2(v[i].y, v[i].w);   // odd parity
        }
    __syncthreads();

    const float* vbase = smem + p * 120 + u0;                    // f1 parity row
    const float* wbase = smem + 240 + q * 240 + p * 120 + u0 + 8 * jh;

    const int NCHUNK = 128 / CC;       // 64
    #pragma unroll 1
    for (int cc = 0; cc < NCHUNK; cc++) {
        const int curo = (cc & 1) * BUFPAD;
        const int nxto = ((cc + 1) & 1) * BUFPAD;

        if (cc + 1 < NCHUNK) {         // LDGs in flight over compute
            #pragma unroll
            for (int i = 0; i < NL; i++)
                if (so[i] >= 0) {
                    gp[i] += CC * CH_STRIDE / 4;
                    v[i] = *gp[i];
                }
        }

        #pragma unroll
        for (int c = 0; c < CC; c++) {
            float4 V = *(const float4*)(vbase + curo + c * CROW);
            const float4* wp = (const float4*)(wbase + curo + c * CROW);
            float4 W0 = wp[0], W1 = wp[1], W2 = wp[2], W3 = wp[3];
            float w[16] = {W0.x, W0.y, W0.z, W0.w, W1.x, W1.y, W1.z, W1.w,
                           W2.x, W2.y, W2.z, W2.w, W3.x, W3.y, W3.z, W3.w};
            float a[4] = {V.x, V.y, V.z, V.w};
            if (jh == 0) {
                // j = jj: slots u0+k+jj, rel k+jj in [0,13]
                #pragma unroll
                for (int k = 0; k < 4; k++)
                    #pragma unroll
                    for (int jj = 0; jj < 11; jj++)
                        acc[k*11 + jj] = fmaf(a[k], w[k + jj], acc[k*11 + jj]);
            } else {
                // j = 10+jj: slots u0+k+10+jj, base u0+8 -> rel k+jj+2 in [2,15]
                #pragma unroll
                for (int k = 0; k < 4; k++)
                    #pragma unroll
                    for (int jj = 0; jj < 11; jj++)
                        acc[k*11 + jj] = fmaf(a[k], w[k + jj + 2], acc[k*11 + jj]);
            }
        }

        if (cc + 1 < NCHUNK) {
            #pragma unroll
            for (int i = 0; i < NL; i++)
                if (so[i] >= 0) {
                    char* d = (char*)smem + nxto * 4 + so[i];
                    *(float2*)(d)       = make_float2(v[i].x, v[i].z);
                    *(float2*)(d + 480) = make_float2(v[i].y, v[i].w);
                }
        }
        __syncthreads();
    }

    // store: j = 10*jh + jj (j=10 double-stored, bitwise identical)
    if (ix < 21) {
        size_t obase = (((size_t)b * 441 + (size_t)ix * 21 + 10 * jh) * 96 + h) * 192
                       + 2 * u0 + p;
        #pragma unroll
        for (int jj = 0; jj < 11; jj++) {
            size_t ob = obase + (size_t)jj * CH_STRIDE;
            #pragma unroll
            for (int k = 0; k < 4; k++)
                out[ob + 2 * k] = acc[k * 11 + jj];
        }
    }
}

extern "C" void kernel_launch(void* const* d_in, const int* in_sizes, int n_in,
                              void* d_out, int out_size)
{
    const float* f1 = (const float*)d_in[0];
    const float* f2 = (const float*)d_in[1];
    float* out = (float*)d_out;

    size_t smem_bytes = (size_t)2 * BUFPAD * sizeof(float);   // 32768 B
    cudaFuncSetAttribute(corr_kernel, cudaFuncAttributeMaxDynamicSharedMemorySize,
                         (int)smem_bytes);

    dim3 grid(96, 4, 11);   // (h, b, ix-pair)
    corr_kernel<<<grid, NTHR, smem_bytes>>>(f1, f2, out);
}